// round 5
// baseline (speedup 1.0000x reference)
#include <cuda_runtime.h>
#include <cuda_fp16.h>
#include <cstdint>
#include <cstddef>

// ============================================================================
// out[4096,4096] = sparse[4096,4096] @ weight[4096,4096] + bias[4096]
// sm_103 (non-'a' PTX target): no tcgen05 / wgmma. Use classic sm_80 path:
// fp16 mma.sync.m16n8k16 with fp32 accumulation, cp.async 4-stage pipeline.
// fp16 operand rounding -> rel_err ~4e-4 < 1e-3 (bf16 would be ~1.6e-3).
// ============================================================================

#define MDIM 4096
#define NDIM 4096
#define KDIM 4096

#define BM 128
#define BN 128
#define BK 32                      // 32 halves = 64 B per SMEM row
#define STAGES 4
#define NKT (KDIM / BK)            // 128
#define ASTAGE_BYTES (BM * BK * 2) // 8192
#define BSTAGE_BYTES (BN * BK * 2) // 8192
#define STAGE_BYTES (ASTAGE_BYTES + BSTAGE_BYTES) // 16384
#define SMEM_TOTAL (STAGES * STAGE_BYTES)         // 65536

// Packed fp16 operands. A: [M][K] row-major. B: [N][K] (i.e., W transposed,
// n-major with k contiguous) so both tiles use the identical SMEM layout and
// non-transposed ldmatrix.
__device__ __align__(16) __half g_A[(size_t)MDIM * KDIM];
__device__ __align__(16) __half g_B[(size_t)NDIM * KDIM];

// ---------------------------------------------------------------------------
__device__ __forceinline__ uint32_t h2_as_u32(__half2 h) {
    return *reinterpret_cast<uint32_t*>(&h);
}

__device__ __forceinline__ uint32_t smem_u32(const void* p) {
    uint32_t a;
    asm("{ .reg .u64 t; cvta.to.shared.u64 t, %1; cvt.u32.u64 %0, t; }" : "=r"(a) : "l"(p));
    return a;
}

__device__ __forceinline__ void cp_async16(uint32_t dst, const void* src) {
    asm volatile("cp.async.cg.shared.global [%0], [%1], 16;" :: "r"(dst), "l"(src));
}

#define LDSM_X4(r, addr)                                                        \
    asm volatile("ldmatrix.sync.aligned.m8n8.x4.shared.b16 {%0,%1,%2,%3}, [%4];" \
                 : "=r"((r)[0]), "=r"((r)[1]), "=r"((r)[2]), "=r"((r)[3])        \
                 : "r"(addr))

__device__ __forceinline__ void mma16816(float* c, const uint32_t* a, uint32_t b0,
                                         uint32_t b1) {
    asm volatile(
        "mma.sync.aligned.m16n8k16.row.col.f32.f16.f16.f32 "
        "{%0,%1,%2,%3}, {%4,%5,%6,%7}, {%8,%9}, {%0,%1,%2,%3};"
        : "+f"(c[0]), "+f"(c[1]), "+f"(c[2]), "+f"(c[3])
        : "r"(a[0]), "r"(a[1]), "r"(a[2]), "r"(a[3]), "r"(b0), "r"(b1));
}

// ---------------------------------------------------------------------------
// pack_x: fp32 [M][K] -> fp16 [M][K]. Pure elementwise convert, vectorized.
// ---------------------------------------------------------------------------
__global__ void pack_x_kernel(const float* __restrict__ x) {
    size_t i = ((size_t)blockIdx.x * blockDim.x + threadIdx.x) * 8;
    float4 v0 = *reinterpret_cast<const float4*>(x + i);
    float4 v1 = *reinterpret_cast<const float4*>(x + i + 4);
    uint4 o;
    o.x = h2_as_u32(__floats2half2_rn(v0.x, v0.y));
    o.y = h2_as_u32(__floats2half2_rn(v0.z, v0.w));
    o.z = h2_as_u32(__floats2half2_rn(v1.x, v1.y));
    o.w = h2_as_u32(__floats2half2_rn(v1.z, v1.w));
    *reinterpret_cast<uint4*>(&g_A[i]) = o;
}

// ---------------------------------------------------------------------------
// pack_w: fp32 W[K][N] -> fp16 g_B[N][K] (transpose + convert) via SMEM tile.
// ---------------------------------------------------------------------------
__global__ void pack_w_kernel(const float* __restrict__ w) {
    __shared__ float tile[64][65];
    int nb = blockIdx.x >> 6, kb = blockIdx.x & 63;
    int tid = threadIdx.x;
#pragma unroll
    for (int i = 0; i < 16; ++i) {
        int lin = tid + i * 256;
        int kk = lin >> 6, nn = lin & 63;
        tile[kk][nn] = w[(size_t)(kb * 64 + kk) * NDIM + (nb * 64 + nn)];
    }
    __syncthreads();
    int nn = tid >> 2;
    int kq = (tid & 3) * 16;
    __half* dst = &g_B[(size_t)(nb * 64 + nn) * KDIM + kb * 64 + kq];
    uint32_t r[8];
#pragma unroll
    for (int j = 0; j < 8; ++j)
        r[j] = h2_as_u32(__floats2half2_rn(tile[kq + 2 * j][nn], tile[kq + 2 * j + 1][nn]));
    *reinterpret_cast<uint4*>(dst) = make_uint4(r[0], r[1], r[2], r[3]);
    *reinterpret_cast<uint4*>(dst + 8) = make_uint4(r[4], r[5], r[6], r[7]);
}

// ---------------------------------------------------------------------------
// GEMM. SMEM tile layout (both A and B): [row][BK halves], 64 B rows, 16 B
// chunk swizzle: chunk' = chunk ^ ((row>>1) & 3) -> conflict-free cp.async
// stores and ldmatrix loads.
// ---------------------------------------------------------------------------
__device__ __forceinline__ void load_stage(uint32_t sb, int stage, const __half* gA,
                                           const __half* gB, int lrow, int lc0, int kt) {
    uint32_t abase = sb + stage * STAGE_BYTES + lrow * 64;
    uint32_t bbase = abase + ASTAGE_BYTES;
    int swz = (lrow >> 1) & 3;
    const char* srcA = (const char*)(gA + (size_t)kt * BK);
    const char* srcB = (const char*)(gB + (size_t)kt * BK);
#pragma unroll
    for (int j = 0; j < 2; ++j) {
        int c = lc0 + j;
        cp_async16(abase + ((c ^ swz) * 16), srcA + c * 16);
        cp_async16(bbase + ((c ^ swz) * 16), srcB + c * 16);
    }
}

__global__ void __launch_bounds__(256, 1)
gemm_kernel(const float* __restrict__ bias, float* __restrict__ out) {
    extern __shared__ unsigned char smem[];
    const uint32_t sb = smem_u32(smem);
    const int tid = threadIdx.x, wid = tid >> 5, lane = tid & 31;
    const int bm = blockIdx.x & 31, bn = blockIdx.x >> 5;
    const int wm = (wid >> 2) * 64, wn = (wid & 3) * 32;

    // cp.async source rows for this thread
    const int lrow = tid >> 1;       // 0..127
    const int lc0 = (tid & 1) * 2;   // chunks {0,1} or {2,3}
    const __half* gA = g_A + (size_t)(bm * BM + lrow) * KDIM;
    const __half* gB = g_B + (size_t)(bn * BN + lrow) * KDIM;

    // Prologue: fill stages 0..2
#pragma unroll
    for (int s = 0; s < STAGES - 1; ++s) {
        load_stage(sb, s, gA, gB, lrow, lc0, s);
        asm volatile("cp.async.commit_group;" ::: "memory");
    }

    float c[4][4][4];
#pragma unroll
    for (int i = 0; i < 4; ++i)
#pragma unroll
        for (int j = 0; j < 4; ++j)
#pragma unroll
            for (int k = 0; k < 4; ++k) c[i][j][k] = 0.f;

    // Precompute ldmatrix row/chunk components (swizzle applied per k-step)
    const int a_row = wm + (lane & 15);                     // + mi*16
    const int a_kh = lane >> 4;                             // k-half select
    const int b_row = wn + (lane & 7) + ((lane >> 4) << 3); // + nj*16
    const int b_kh = (lane >> 3) & 1;

    for (int kt = 0; kt < NKT; ++kt) {
        const int stage = kt & (STAGES - 1);
        asm volatile("cp.async.wait_group %0;" :: "n"(STAGES - 2) : "memory");
        __syncthreads();
        if (kt + STAGES - 1 < NKT)
            load_stage(sb, (kt + STAGES - 1) & (STAGES - 1), gA, gB, lrow, lc0,
                       kt + STAGES - 1);
        asm volatile("cp.async.commit_group;" ::: "memory");

        const uint32_t aT = sb + stage * STAGE_BYTES;
        const uint32_t bT = aT + ASTAGE_BYTES;
#pragma unroll
        for (int ks = 0; ks < 2; ++ks) {
            uint32_t a[4][4], b[2][4];
#pragma unroll
            for (int mi = 0; mi < 4; ++mi) {
                int row = a_row + mi * 16;
                int ch = ks * 2 + a_kh;
                uint32_t addr = aT + row * 64 + ((ch ^ ((row >> 1) & 3)) * 16);
                LDSM_X4(a[mi], addr);
            }
#pragma unroll
            for (int nj = 0; nj < 2; ++nj) {
                int row = b_row + nj * 16;
                int ch = ks * 2 + b_kh;
                uint32_t addr = bT + row * 64 + ((ch ^ ((row >> 1) & 3)) * 16);
                LDSM_X4(b[nj], addr);
            }
#pragma unroll
            for (int mi = 0; mi < 4; ++mi)
#pragma unroll
                for (int ni = 0; ni < 4; ++ni)
                    mma16816(c[mi][ni], a[mi], b[ni >> 1][(ni & 1) * 2],
                             b[ni >> 1][(ni & 1) * 2 + 1]);
        }
    }

    // Epilogue: add bias, store fp32.
    const int g = lane >> 2, t2 = (lane & 3) * 2;
#pragma unroll
    for (int mi = 0; mi < 4; ++mi) {
        const int m = bm * BM + wm + mi * 16 + g;
#pragma unroll
        for (int ni = 0; ni < 4; ++ni) {
            const int n = bn * BN + wn + ni * 8 + t2;
            const float b0 = bias[n], b1 = bias[n + 1];
            float2 v0 = {c[mi][ni][0] + b0, c[mi][ni][1] + b1};
            float2 v1 = {c[mi][ni][2] + b0, c[mi][ni][3] + b1};
            *reinterpret_cast<float2*>(out + (size_t)m * NDIM + n) = v0;
            *reinterpret_cast<float2*>(out + (size_t)(m + 8) * NDIM + n) = v1;
        }
    }
}

// ---------------------------------------------------------------------------
extern "C" void kernel_launch(void* const* d_in, const int* in_sizes, int n_in,
                              void* d_out, int out_size) {
    const float* x = (const float*)d_in[0];  // sparse [4096,4096]
    const float* w = (const float*)d_in[1];  // weight [4096,4096] (in,out)
    const float* b = (const float*)d_in[2];  // bias [4096]
    float* out = (float*)d_out;

    cudaFuncSetAttribute(gemm_kernel, cudaFuncAttributeMaxDynamicSharedMemorySize,
                         SMEM_TOTAL);

    pack_x_kernel<<<(MDIM * KDIM) / (256 * 8), 256>>>(x);
    pack_w_kernel<<<(KDIM / 64) * (NDIM / 64), 256>>>(w);
    gemm_kernel<<<(MDIM / BM) * (NDIM / BN), 256, SMEM_TOTAL>>>(b, out);
}